// round 15
// baseline (speedup 1.0000x reference)
#include <cuda_runtime.h>
#include <cuda_bf16.h>
#include <cstdint>
#include <math.h>

#define BATCH 8
#define CCH   512
#define NTOK  1024
#define HEADS 8
#define HD    64
#define EPS   1e-5f
#define ELEMS (BATCH * CCH * NTOK)
#define WELEMS (CCH * CCH)
#define QSCALE (0.125f * 1.4426950408889634f)

typedef __nv_bfloat16 bf16;

// Scratch (allocation-free rule: device globals)
__device__ bf16 g_xnt[ELEMS];        // [b][n][c] token-major
__device__ bf16 g_qt [ELEMS];        // [b][n][c] (pre-scaled by 0.125*log2e)
__device__ bf16 g_kt [ELEMS];        // [b][n][c]
__device__ bf16 g_v  [ELEMS];        // [b][c][n] channel-major
__device__ bf16 g_aot[ELEMS];        // [b][n][c]
__device__ bf16 g_wr [4 * WELEMS];   // bf16 weights q,k,v,o

// ---------------------------------------------------------------------------
// Helpers
// ---------------------------------------------------------------------------
__device__ __forceinline__ uint32_t smem_u32(const void* p) {
    uint32_t a;
    asm("{ .reg .u64 t; cvta.to.shared.u64 t, %1; cvt.u32.u64 %0, t; }"
        : "=r"(a) : "l"(p));
    return a;
}
__device__ __forceinline__ void cp16(uint32_t sdst, const void* gsrc) {
    asm volatile("cp.async.cg.shared.global [%0], [%1], 16;"
                 :: "r"(sdst), "l"(gsrc) : "memory");
}
__device__ __forceinline__ void cp_commit() {
    asm volatile("cp.async.commit_group;" ::: "memory");
}
template <int N>
__device__ __forceinline__ void cp_wait() {
    asm volatile("cp.async.wait_group %0;" :: "n"(N) : "memory");
}
__device__ __forceinline__ void ldsm_x4(uint32_t* r, uint32_t addr) {
    asm volatile("ldmatrix.sync.aligned.m8n8.x4.shared.b16 {%0,%1,%2,%3}, [%4];"
                 : "=r"(r[0]), "=r"(r[1]), "=r"(r[2]), "=r"(r[3]) : "r"(addr));
}
__device__ __forceinline__ void mma_bf16(float* c, const uint32_t* a,
                                         const uint32_t* b) {
    asm volatile("mma.sync.aligned.m16n8k16.row.col.f32.bf16.bf16.f32 "
                 "{%0,%1,%2,%3}, {%4,%5,%6,%7}, {%8,%9}, {%0,%1,%2,%3};"
                 : "+f"(c[0]), "+f"(c[1]), "+f"(c[2]), "+f"(c[3])
                 : "r"(a[0]), "r"(a[1]), "r"(a[2]), "r"(a[3]),
                   "r"(b[0]), "r"(b[1]));
}
__device__ __forceinline__ uint32_t pack2(float hi, float lo) {
    uint32_t d;
    asm("cvt.rn.bf16x2.f32 %0, %1, %2;" : "=r"(d) : "f"(hi), "f"(lo));
    return d;
}
__device__ __forceinline__ uint32_t ex2_bf16x2(uint32_t x) {
    uint32_t d;
    asm("ex2.approx.ftz.bf16x2 %0, %1;" : "=r"(d) : "r"(x));
    return d;
}

// ---------------------------------------------------------------------------
// bf16 GEMM core: C[128x128] = A[128xK] * B[128xK]^T, K=512,
// K-chunk 64, 3-stage cp.async. 256 threads (8 warps 2x4). acc[4][4][4].
// ---------------------------------------------------------------------------
#define BSTR 72
#define STG  (2 * 128 * BSTR)
#define GEMM_SMEM (3 * STG * 2)               // 110592 B

__device__ __forceinline__ void ld_stage(bf16* dst, const bf16* A, int as,
                                         const bf16* B, int bs, int tid) {
    #pragma unroll
    for (int it = 0; it < 4; it++) {
        int idx = tid + it * 256;
        int row = idx >> 3, c = (idx & 7) * 8;
        cp16(smem_u32(dst + row * BSTR + c), A + (size_t)row * as + c);
    }
    bf16* db = dst + 128 * BSTR;
    #pragma unroll
    for (int it = 0; it < 4; it++) {
        int idx = tid + it * 256;
        int row = idx >> 3, c = (idx & 7) * 8;
        cp16(smem_u32(db + row * BSTR + c), B + (size_t)row * bs + c);
    }
}

__device__ __forceinline__ void gemm_bf16(bf16* sm, const bf16* A, int as,
                                          const bf16* B, int bs,
                                          float acc[4][4][4]) {
    int tid = threadIdx.x, wid = tid >> 5, lane = tid & 31;
    int wm0 = (wid >> 2) * 64, wn0 = (wid & 3) * 32;
    int arow = (lane & 7) + ((lane >> 3) & 1) * 8;
    int acol = (lane >> 4) * 8;
    int brow = (lane & 7) + ((lane >= 16) ? 8 : 0);
    int bcol = ((lane >> 3) & 1) * 8;

    #pragma unroll
    for (int mi = 0; mi < 4; mi++)
        #pragma unroll
        for (int ni = 0; ni < 4; ni++)
            #pragma unroll
            for (int r = 0; r < 4; r++) acc[mi][ni][r] = 0.f;

    ld_stage(sm, A, as, B, bs, tid);
    cp_commit();
    ld_stage(sm + STG, A + 64, as, B + 64, bs, tid);
    cp_commit();

    uint32_t abase[4], bbase[2];
    #pragma unroll
    for (int mi = 0; mi < 4; mi++)
        abase[mi] = smem_u32(sm + (wm0 + mi * 16 + arow) * BSTR + acol);
    #pragma unroll
    for (int np = 0; np < 2; np++)
        bbase[np] = smem_u32(sm + 128 * BSTR + (wn0 + np * 16 + brow) * BSTR + bcol);

    for (int i = 0; i < 8; i++) {
        cp_wait<1>();
        __syncthreads();
        if (i + 2 < 8)
            ld_stage(sm + ((i + 2) % 3) * STG, A + (size_t)(i + 2) * 64, as,
                     B + (size_t)(i + 2) * 64, bs, tid);
        cp_commit();

        uint32_t stoff = (uint32_t)((i % 3) * (STG * 2));
        #pragma unroll
        for (int ks = 0; ks < 4; ks++) {
            uint32_t ko = stoff + ks * 32;
            uint32_t af[4][4];
            #pragma unroll
            for (int mi = 0; mi < 4; mi++)
                ldsm_x4(af[mi], abase[mi] + ko);
            #pragma unroll
            for (int np = 0; np < 2; np++) {
                uint32_t bq[4];
                ldsm_x4(bq, bbase[np] + ko);
                #pragma unroll
                for (int mi = 0; mi < 4; mi++) {
                    mma_bf16(acc[mi][2 * np],     af[mi], bq);
                    mma_bf16(acc[mi][2 * np + 1], af[mi], bq + 2);
                }
            }
        }
    }
    __syncthreads();
}

// ---------------------------------------------------------------------------
// Weight conversion
// ---------------------------------------------------------------------------
__global__ __launch_bounds__(256) void prep_w_kernel(const float* __restrict__ qw,
                                                     const float* __restrict__ kw,
                                                     const float* __restrict__ vw,
                                                     const float* __restrict__ ow) {
    int i4 = (blockIdx.x * 256 + threadIdx.x) * 4;
    #pragma unroll
    for (int w = 0; w < 4; w++) {
        const float* src = (w == 0) ? qw : (w == 1) ? kw : (w == 2) ? vw : ow;
        float4 v = *(const float4*)(src + i4);
        uint2 p;
        p.x = pack2(v.y, v.x);
        p.y = pack2(v.w, v.z);
        *(uint2*)(g_wr + w * WELEMS + i4) = p;
    }
}

// ---------------------------------------------------------------------------
// GroupNorm (per batch-chunk; single-pass, x tile cached in smem)
// ---------------------------------------------------------------------------
#define XS_STR 1032
#define PREP_SMEM (16 * XS_STR * 4)   // 66048 B

__global__ __launch_bounds__(256) void gn_kernel(const float* __restrict__ x,
                                                 const float* __restrict__ gw,
                                                 const float* __restrict__ gb,
                                                 int b0) {
    extern __shared__ float xs[];
    int bg = blockIdx.x;
    int b = b0 + (bg >> 5), g = bg & 31;
    const float* xp = x + ((size_t)b * CCH + g * 16) * NTOK;
    const float4* xp4 = (const float4*)xp;

    float s = 0.f, ss = 0.f;
    #pragma unroll
    for (int it = 0; it < 16; it++) {
        int idx4 = threadIdx.x + it * 256;
        int c = idx4 >> 8, q = idx4 & 255;
        float4 v = xp4[c * 256 + q];
        *(float4*)&xs[c * XS_STR + q * 4] = v;
        s += v.x + v.y + v.z + v.w;
        ss += v.x * v.x + v.y * v.y + v.z * v.z + v.w * v.w;
    }
    __shared__ float rs[8], rss[8];
    #pragma unroll
    for (int o = 16; o > 0; o >>= 1) {
        s  += __shfl_xor_sync(~0u, s,  o);
        ss += __shfl_xor_sync(~0u, ss, o);
    }
    int wid = threadIdx.x >> 5, lane = threadIdx.x & 31;
    if (lane == 0) { rs[wid] = s; rss[wid] = ss; }
    __syncthreads();
    if (wid == 0) {
        s  = (lane < 8) ? rs[lane]  : 0.f;
        ss = (lane < 8) ? rss[lane] : 0.f;
        #pragma unroll
        for (int o = 4; o > 0; o >>= 1) {
            s  += __shfl_xor_sync(~0u, s,  o);
            ss += __shfl_xor_sync(~0u, ss, o);
        }
        if (lane == 0) { rs[0] = s; rss[0] = ss; }
    }
    __syncthreads();
    const float inv_n = 1.f / (16.f * NTOK);
    float mu  = rs[0] * inv_n;
    float var = rss[0] * inv_n - mu * mu;
    float inv = rsqrtf(var + EPS);

    __shared__ float ts[16][65];
    __shared__ float wc[16], bc[16];
    if (threadIdx.x < 16) {
        wc[threadIdx.x] = gw[g * 16 + threadIdx.x] * inv;
        bc[threadIdx.x] = gb[g * 16 + threadIdx.x];
    }
    __syncthreads();

    for (int j = 0; j < 16; j++) {
        for (int idx = threadIdx.x; idx < 1024; idx += 256) {
            int c = idx >> 6, n = idx & 63;
            float v = xs[c * XS_STR + j * 64 + n];
            ts[c][n] = (v - mu) * wc[c] + bc[c];
        }
        __syncthreads();
        for (int idx = threadIdx.x; idx < 1024; idx += 256) {
            int n = idx >> 4, c = idx & 15;
            g_xnt[((size_t)b * NTOK + j * 64 + n) * CCH + g * 16 + c] =
                __float2bfloat16(ts[c][n]);
        }
        __syncthreads();
    }
}

// ---------------------------------------------------------------------------
// Merged QKV projection (batch-chunk). blockIdx.y: 0-3 Q, 4-7 K, 8-11 V.
// ---------------------------------------------------------------------------
__global__ __launch_bounds__(256, 2) void qkv_kernel(const bf16* __restrict__ X,
                                                     const float* __restrict__ qb,
                                                     const float* __restrict__ kb,
                                                     const float* __restrict__ vb,
                                                     int b0) {
    extern __shared__ bf16 smb[];
    int n0 = blockIdx.x * 128, y = blockIdx.y, b = b0 + blockIdx.z;
    int m0 = y * 128;
    float acc[4][4][4];
    gemm_bf16(smb, g_wr + (size_t)m0 * CCH, CCH,
              X + ((size_t)b * NTOK + n0) * CCH, CCH, acc);

    int tid = threadIdx.x, wid = tid >> 5, lane = tid & 31;
    int g = lane >> 2, t = lane & 3;
    int wm0 = (wid >> 2) * 64, wn0 = (wid & 3) * 32;

    if (y < 8) {
        float scale = (y < 4) ? QSCALE : 1.0f;
        const float* bias = (y < 4) ? qb : kb;
        bf16* out = (y < 4) ? g_qt : g_kt;
        int mb = m0 & 511;
        #pragma unroll
        for (int mi = 0; mi < 4; mi++) {
            int m = wm0 + mi * 16 + g;
            float b0v = bias[mb + m], b1v = bias[mb + m + 8];
            #pragma unroll
            for (int ni = 0; ni < 4; ni++) {
                const float* c = acc[mi][ni];
                int n = wn0 + ni * 8 + t * 2;
                smb[n * 136 + m]           = __float2bfloat16((c[0] + b0v) * scale);
                smb[(n + 1) * 136 + m]     = __float2bfloat16((c[1] + b0v) * scale);
                smb[n * 136 + m + 8]       = __float2bfloat16((c[2] + b1v) * scale);
                smb[(n + 1) * 136 + m + 8] = __float2bfloat16((c[3] + b1v) * scale);
            }
        }
        __syncthreads();
        bf16* ob = out + ((size_t)b * NTOK + n0) * CCH + mb;
        #pragma unroll
        for (int it = 0; it < 8; it++) {
            int idx = tid + it * 256;
            int n = idx >> 4, c8 = (idx & 15) * 8;
            float4 v = *(const float4*)(smb + n * 136 + c8);
            *(float4*)(ob + (size_t)n * CCH + c8) = v;
        }
    } else {
        int mb = m0 - 1024;
        #pragma unroll
        for (int mi = 0; mi < 4; mi++) {
            int m = wm0 + mi * 16 + g;
            float b0v = vb[mb + m], b1v = vb[mb + m + 8];
            #pragma unroll
            for (int ni = 0; ni < 4; ni++) {
                const float* c = acc[mi][ni];
                int n = wn0 + ni * 8 + t * 2;
                *(uint32_t*)&smb[m * 136 + n]       = pack2(c[1] + b0v, c[0] + b0v);
                *(uint32_t*)&smb[(m + 8) * 136 + n] = pack2(c[3] + b1v, c[2] + b1v);
            }
        }
        __syncthreads();
        bf16* ob = g_v + ((size_t)b * CCH + mb) * NTOK + n0;
        #pragma unroll
        for (int it = 0; it < 8; it++) {
            int idx = tid + it * 256;
            int m = idx >> 4, n8 = (idx & 15) * 8;
            float4 v = *(const float4*)(smb + m * 136 + n8);
            *(float4*)(ob + (size_t)m * NTOK + n8) = v;
        }
    }
}

// ---------------------------------------------------------------------------
// Output projection (batch-chunk): fp32 out + bias + residual
// ---------------------------------------------------------------------------
__global__ __launch_bounds__(256, 2) void conv_o_kernel(const bf16* __restrict__ X,
                                                        const float* __restrict__ bias,
                                                        const float* __restrict__ resid,
                                                        float* __restrict__ out,
                                                        int b0) {
    extern __shared__ bf16 smb[];
    int n0 = blockIdx.x * 128, m0 = blockIdx.y * 128, b = b0 + blockIdx.z;
    float acc[4][4][4];
    gemm_bf16(smb, g_wr + 3 * WELEMS + (size_t)m0 * CCH, CCH,
              X + ((size_t)b * NTOK + n0) * CCH, CCH, acc);

    int tid = threadIdx.x, wid = tid >> 5, lane = tid & 31;
    int g = lane >> 2, t = lane & 3;
    int wm0 = (wid >> 2) * 64, wn0 = (wid & 3) * 32;

    float* smf = (float*)smb;
    #pragma unroll
    for (int mi = 0; mi < 4; mi++) {
        int m = wm0 + mi * 16 + g;
        float b0v = bias[m0 + m], b1v = bias[m0 + m + 8];
        #pragma unroll
        for (int ni = 0; ni < 4; ni++) {
            const float* c = acc[mi][ni];
            int n = wn0 + ni * 8 + t * 2;
            smf[m * 132 + n]           = c[0] + b0v;
            smf[m * 132 + n + 1]       = c[1] + b0v;
            smf[(m + 8) * 132 + n]     = c[2] + b1v;
            smf[(m + 8) * 132 + n + 1] = c[3] + b1v;
        }
    }
    __syncthreads();

    #pragma unroll
    for (int it = 0; it < 16; it++) {
        int idx4 = tid + it * 256;
        int m = idx4 >> 5, nq = (idx4 & 31) * 4;
        size_t o = ((size_t)b * CCH + m0 + m) * NTOK + n0 + nq;
        float4 r = *(const float4*)&resid[o];
        float4 v = make_float4(smf[m * 132 + nq]     + r.x,
                               smf[m * 132 + nq + 1] + r.y,
                               smf[m * 132 + nq + 2] + r.z,
                               smf[m * 132 + nq + 3] + r.w);
        *(float4*)&out[o] = v;
    }
}

// ---------------------------------------------------------------------------
// Fused flash attention (batch-chunk), no-max softmax in bf16 (ex2.bf16x2),
// row-sum via ones-MMA. CTA = (128 queries, bh), kv tiles 64, 3-stage.
// ---------------------------------------------------------------------------
#define KSTR 72
#define FSTG (2 * 64 * KSTR)
#define VOFF (64 * KSTR * 2)
#define FLASH_SMEM ((128 * KSTR + 3 * FSTG) * 2)  // 73728 B
#define ONES2 0x3F803F80u

__device__ __forceinline__ void load_kv(bf16* dst, const bf16* ksrc,
                                        const bf16* vsrc, int tid) {
    #pragma unroll
    for (int it = 0; it < 2; it++) {
        int idx = tid + it * 256;
        int r = idx >> 3, c = (idx & 7) * 8;
        cp16(smem_u32(dst + r * KSTR + c), ksrc + (size_t)r * CCH + c);
    }
    bf16* vd = dst + 64 * KSTR;
    #pragma unroll
    for (int it = 0; it < 2; it++) {
        int idx = tid + it * 256;
        int r = idx >> 3, c = (idx & 7) * 8;
        cp16(smem_u32(vd + r * KSTR + c), vsrc + (size_t)r * NTOK + c);
    }
}

__global__ __launch_bounds__(256, 2) void flash_kernel(int bh0) {
    extern __shared__ bf16 smb[];
    bf16* Qs = smb;
    bf16* St = smb + 128 * KSTR;

    int q0 = blockIdx.x * 128, bh = bh0 + blockIdx.y;
    int b = bh >> 3, h = bh & 7;
    const bf16* qp = g_qt + ((size_t)b * NTOK + q0) * CCH + h * HD;
    const bf16* kp = g_kt + (size_t)b * NTOK * CCH + h * HD;
    const bf16* vp = g_v + ((size_t)b * CCH + h * HD) * NTOK;

    int tid = threadIdx.x, wid = tid >> 5, lane = tid & 31;
    int g = lane >> 2, t = lane & 3;
    int wm = wid * 16;
    int arow = (lane & 7) + ((lane >> 3) & 1) * 8;
    int acol = (lane >> 4) * 8;
    int brow = (lane & 7) + ((lane >= 16) ? 8 : 0);
    int bcol = ((lane >> 3) & 1) * 8;

    #pragma unroll
    for (int it = 0; it < 4; it++) {
        int idx = tid + it * 256;
        int r = idx >> 3, c = (idx & 7) * 8;
        cp16(smem_u32(Qs + r * KSTR + c), qp + (size_t)r * CCH + c);
    }
    load_kv(St, kp, vp, tid);
    cp_commit();
    load_kv(St + FSTG, kp + (size_t)64 * CCH, vp + 64, tid);
    cp_commit();

    uint32_t kbase[4];
    #pragma unroll
    for (int np = 0; np < 4; np++)
        kbase[np] = smem_u32(St + (np * 16 + brow) * KSTR + bcol);

    float oacc[8][4];
    #pragma unroll
    for (int ni = 0; ni < 8; ni++)
        #pragma unroll
        for (int r = 0; r < 4; r++) oacc[ni][r] = 0.f;
    float lacc[4] = {0.f, 0.f, 0.f, 0.f};
    const uint32_t ones[2] = {ONES2, ONES2};
    uint32_t qf[4][4];

    for (int kt = 0; kt < 16; kt++) {
        cp_wait<1>();
        __syncthreads();
        if (kt + 2 < 16)
            load_kv(St + ((kt + 2) % 3) * FSTG,
                    kp + (size_t)(kt + 2) * 64 * CCH, vp + (kt + 2) * 64, tid);
        cp_commit();

        if (kt == 0) {
            #pragma unroll
            for (int ks = 0; ks < 4; ks++)
                ldsm_x4(qf[ks], smem_u32(Qs + (wm + arow) * KSTR + ks * 16 + acol));
        }
        uint32_t stoff = (uint32_t)((kt % 3) * (FSTG * 2));

        float sacc[8][4];
        #pragma unroll
        for (int nt = 0; nt < 8; nt++)
            #pragma unroll
            for (int r = 0; r < 4; r++) sacc[nt][r] = 0.f;
        #pragma unroll
        for (int ks = 0; ks < 4; ks++) {
            #pragma unroll
            for (int np = 0; np < 4; np++) {
                uint32_t bq[4];
                ldsm_x4(bq, kbase[np] + stoff + ks * 32);
                mma_bf16(sacc[2 * np],     qf[ks], bq);
                mma_bf16(sacc[2 * np + 1], qf[ks], bq + 2);
            }
        }

        #pragma unroll
        for (int j = 0; j < 4; j++) {
            uint32_t pf[4];
            pf[0] = ex2_bf16x2(pack2(sacc[2 * j][1],     sacc[2 * j][0]));
            pf[1] = ex2_bf16x2(pack2(sacc[2 * j][3],     sacc[2 * j][2]));
            pf[2] = ex2_bf16x2(pack2(sacc[2 * j + 1][1], sacc[2 * j + 1][0]));
            pf[3] = ex2_bf16x2(pack2(sacc[2 * j + 1][3], sacc[2 * j + 1][2]));
            mma_bf16(lacc, pf, ones);
            #pragma unroll
            for (int np = 0; np < 4; np++) {
                uint32_t bq[4];
                ldsm_x4(bq, kbase[np] + stoff + VOFF + j * 32);
                mma_bf16(oacc[2 * np],     pf, bq);
                mma_bf16(oacc[2 * np + 1], pf, bq + 2);
            }
        }
    }

    float i0 = 1.f / lacc[0], i1 = 1.f / lacc[2];
    bf16* ob = g_aot + ((size_t)b * NTOK + q0 + wm) * CCH + h * HD;
    #pragma unroll
    for (int ni = 0; ni < 8; ni++) {
        int d = ni * 8 + t * 2;
        *(__nv_bfloat162*)(ob + (size_t)g * CCH + d) =
            __floats2bfloat162_rn(oacc[ni][0] * i0, oacc[ni][1] * i0);
        *(__nv_bfloat162*)(ob + (size_t)(g + 8) * CCH + d) =
            __floats2bfloat162_rn(oacc[ni][2] * i1, oacc[ni][3] * i1);
    }
}

// ---------------------------------------------------------------------------
extern "C" void kernel_launch(void* const* d_in, const int* in_sizes, int n_in,
                              void* d_out, int out_size) {
    const float* x   = (const float*)d_in[0];
    const float* gnw = (const float*)d_in[1];
    const float* gnb = (const float*)d_in[2];
    const float* qw  = (const float*)d_in[3];
    const float* qb  = (const float*)d_in[4];
    const float* kw  = (const float*)d_in[5];
    const float* kb  = (const float*)d_in[6];
    const float* vw  = (const float*)d_in[7];
    const float* vb  = (const float*)d_in[8];
    const float* ow  = (const float*)d_in[9];
    const float* ob  = (const float*)d_in[10];
    float* out = (float*)d_out;

    void *p_xnt, *p_aot;
    cudaGetSymbolAddress(&p_xnt, g_xnt);
    cudaGetSymbolAddress(&p_aot, g_aot);
    bf16* xnt = (bf16*)p_xnt;
    bf16* aot = (bf16*)p_aot;

    // One-time host resources (2-stream fork/join topology, teardown-clean)
    static cudaStream_t s2 = nullptr;
    static cudaEvent_t evFork = nullptr, evW = nullptr, evJoin = nullptr;
    if (!s2) {
        cudaStreamCreateWithFlags(&s2, cudaStreamNonBlocking);
        cudaEventCreateWithFlags(&evFork, cudaEventDisableTiming);
        cudaEventCreateWithFlags(&evW,    cudaEventDisableTiming);
        cudaEventCreateWithFlags(&evJoin, cudaEventDisableTiming);
        cudaFuncSetAttribute(gn_kernel,     cudaFuncAttributeMaxDynamicSharedMemorySize, PREP_SMEM);
        cudaFuncSetAttribute(qkv_kernel,    cudaFuncAttributeMaxDynamicSharedMemorySize, GEMM_SMEM);
        cudaFuncSetAttribute(conv_o_kernel, cudaFuncAttributeMaxDynamicSharedMemorySize, GEMM_SMEM);
        cudaFuncSetAttribute(flash_kernel,  cudaFuncAttributeMaxDynamicSharedMemorySize, FLASH_SMEM);
    }

    // Fork
    cudaEventRecord(evFork, 0);
    cudaStreamWaitEvent(s2, evFork, 0);

    // Asymmetric split: stream0 = batches 0-4 (5), stream1 = batches 5-7 (3).
    // Stream1 also owns the tiny prep_w; stream0's qkv waits on evW.
    dim3 gq0(NTOK / 128, 12, 5), gq1(NTOK / 128, 12, 3);
    dim3 gf0(NTOK / 128, 5 * HEADS), gf1(NTOK / 128, 3 * HEADS);
    dim3 gg0(NTOK / 128, CCH / 128, 5), gg1(NTOK / 128, CCH / 128, 3);

    // Stream 1 (lighter): weights first, then GN(5-7) and its chain
    prep_w_kernel<<<256, 256, 0, s2>>>(qw, kw, vw, ow);
    cudaEventRecord(evW, s2);
    gn_kernel<<<96, 256, PREP_SMEM, s2>>>(x, gnw, gnb, 5);
    qkv_kernel<<<gq1, 256, GEMM_SMEM, s2>>>(xnt, qb, kb, vb, 5);
    flash_kernel<<<gf1, 256, FLASH_SMEM, s2>>>(40);
    conv_o_kernel<<<gg1, 256, GEMM_SMEM, s2>>>(aot, ob, x, out, 5);

    // Stream 0 (heavier): GN(0-4) immediately (no weight dep), wait evW, chain
    gn_kernel<<<160, 256, PREP_SMEM>>>(x, gnw, gnb, 0);
    cudaStreamWaitEvent(0, evW, 0);
    qkv_kernel<<<gq0, 256, GEMM_SMEM>>>(xnt, qb, kb, vb, 0);
    flash_kernel<<<gf0, 256, FLASH_SMEM>>>(0);
    conv_o_kernel<<<gg0, 256, GEMM_SMEM>>>(aot, ob, x, out, 0);

    // Join
    cudaEventRecord(evJoin, s2);
    cudaStreamWaitEvent(0, evJoin, 0);
}

// round 16
// speedup vs baseline: 1.0462x; 1.0462x over previous
#include <cuda_runtime.h>
#include <cuda_bf16.h>
#include <cstdint>
#include <math.h>

#define BATCH 8
#define CCH   512
#define NTOK  1024
#define HEADS 8
#define HD    64
#define EPS   1e-5f
#define ELEMS (BATCH * CCH * NTOK)
#define WELEMS (CCH * CCH)
#define QSCALE (0.125f * 1.4426950408889634f)

typedef __nv_bfloat16 bf16;

// Scratch (allocation-free rule: device globals)
__device__ bf16 g_xnt[ELEMS];        // [b][n][c] token-major
__device__ bf16 g_qt [ELEMS];        // [b][n][c] (pre-scaled by 0.125*log2e)
__device__ bf16 g_kt [ELEMS];        // [b][n][c]
__device__ bf16 g_v  [ELEMS];        // [b][c][n] channel-major
__device__ bf16 g_aot[ELEMS];        // [b][n][c]
__device__ bf16 g_wr [4 * WELEMS];   // bf16 weights q,k,v,o

// ---------------------------------------------------------------------------
// Helpers
// ---------------------------------------------------------------------------
__device__ __forceinline__ uint32_t smem_u32(const void* p) {
    uint32_t a;
    asm("{ .reg .u64 t; cvta.to.shared.u64 t, %1; cvt.u32.u64 %0, t; }"
        : "=r"(a) : "l"(p));
    return a;
}
__device__ __forceinline__ void cp16(uint32_t sdst, const void* gsrc) {
    asm volatile("cp.async.cg.shared.global [%0], [%1], 16;"
                 :: "r"(sdst), "l"(gsrc) : "memory");
}
__device__ __forceinline__ void cp_commit() {
    asm volatile("cp.async.commit_group;" ::: "memory");
}
template <int N>
__device__ __forceinline__ void cp_wait() {
    asm volatile("cp.async.wait_group %0;" :: "n"(N) : "memory");
}
__device__ __forceinline__ void ldsm_x4(uint32_t* r, uint32_t addr) {
    asm volatile("ldmatrix.sync.aligned.m8n8.x4.shared.b16 {%0,%1,%2,%3}, [%4];"
                 : "=r"(r[0]), "=r"(r[1]), "=r"(r[2]), "=r"(r[3]) : "r"(addr));
}
__device__ __forceinline__ void mma_bf16(float* c, const uint32_t* a,
                                         const uint32_t* b) {
    asm volatile("mma.sync.aligned.m16n8k16.row.col.f32.bf16.bf16.f32 "
                 "{%0,%1,%2,%3}, {%4,%5,%6,%7}, {%8,%9}, {%0,%1,%2,%3};"
                 : "+f"(c[0]), "+f"(c[1]), "+f"(c[2]), "+f"(c[3])
                 : "r"(a[0]), "r"(a[1]), "r"(a[2]), "r"(a[3]),
                   "r"(b[0]), "r"(b[1]));
}
__device__ __forceinline__ uint32_t pack2(float hi, float lo) {
    uint32_t d;
    asm("cvt.rn.bf16x2.f32 %0, %1, %2;" : "=r"(d) : "f"(hi), "f"(lo));
    return d;
}
__device__ __forceinline__ uint32_t ex2_bf16x2(uint32_t x) {
    uint32_t d;
    asm("ex2.approx.ftz.bf16x2 %0, %1;" : "=r"(d) : "r"(x));
    return d;
}

// ---------------------------------------------------------------------------
// bf16 GEMM core: C[128x128] = A[128xK] * B[128xK]^T, K=512,
// K-chunk 64, 3-stage cp.async. 256 threads (8 warps 2x4). acc[4][4][4].
// ---------------------------------------------------------------------------
#define BSTR 72
#define STG  (2 * 128 * BSTR)
#define GEMM_SMEM (3 * STG * 2)               // 110592 B

__device__ __forceinline__ void ld_stage(bf16* dst, const bf16* A, int as,
                                         const bf16* B, int bs, int tid) {
    #pragma unroll
    for (int it = 0; it < 4; it++) {
        int idx = tid + it * 256;
        int row = idx >> 3, c = (idx & 7) * 8;
        cp16(smem_u32(dst + row * BSTR + c), A + (size_t)row * as + c);
    }
    bf16* db = dst + 128 * BSTR;
    #pragma unroll
    for (int it = 0; it < 4; it++) {
        int idx = tid + it * 256;
        int row = idx >> 3, c = (idx & 7) * 8;
        cp16(smem_u32(db + row * BSTR + c), B + (size_t)row * bs + c);
    }
}

__device__ __forceinline__ void gemm_bf16(bf16* sm, const bf16* A, int as,
                                          const bf16* B, int bs,
                                          float acc[4][4][4]) {
    int tid = threadIdx.x, wid = tid >> 5, lane = tid & 31;
    int wm0 = (wid >> 2) * 64, wn0 = (wid & 3) * 32;
    int arow = (lane & 7) + ((lane >> 3) & 1) * 8;
    int acol = (lane >> 4) * 8;
    int brow = (lane & 7) + ((lane >= 16) ? 8 : 0);
    int bcol = ((lane >> 3) & 1) * 8;

    #pragma unroll
    for (int mi = 0; mi < 4; mi++)
        #pragma unroll
        for (int ni = 0; ni < 4; ni++)
            #pragma unroll
            for (int r = 0; r < 4; r++) acc[mi][ni][r] = 0.f;

    ld_stage(sm, A, as, B, bs, tid);
    cp_commit();
    ld_stage(sm + STG, A + 64, as, B + 64, bs, tid);
    cp_commit();

    uint32_t abase[4], bbase[2];
    #pragma unroll
    for (int mi = 0; mi < 4; mi++)
        abase[mi] = smem_u32(sm + (wm0 + mi * 16 + arow) * BSTR + acol);
    #pragma unroll
    for (int np = 0; np < 2; np++)
        bbase[np] = smem_u32(sm + 128 * BSTR + (wn0 + np * 16 + brow) * BSTR + bcol);

    for (int i = 0; i < 8; i++) {
        cp_wait<1>();
        __syncthreads();
        if (i + 2 < 8)
            ld_stage(sm + ((i + 2) % 3) * STG, A + (size_t)(i + 2) * 64, as,
                     B + (size_t)(i + 2) * 64, bs, tid);
        cp_commit();

        uint32_t stoff = (uint32_t)((i % 3) * (STG * 2));
        #pragma unroll
        for (int ks = 0; ks < 4; ks++) {
            uint32_t ko = stoff + ks * 32;
            uint32_t af[4][4];
            #pragma unroll
            for (int mi = 0; mi < 4; mi++)
                ldsm_x4(af[mi], abase[mi] + ko);
            #pragma unroll
            for (int np = 0; np < 2; np++) {
                uint32_t bq[4];
                ldsm_x4(bq, bbase[np] + ko);
                #pragma unroll
                for (int mi = 0; mi < 4; mi++) {
                    mma_bf16(acc[mi][2 * np],     af[mi], bq);
                    mma_bf16(acc[mi][2 * np + 1], af[mi], bq + 2);
                }
            }
        }
    }
    __syncthreads();
}

// ---------------------------------------------------------------------------
// Weight conversion
// ---------------------------------------------------------------------------
__global__ __launch_bounds__(256) void prep_w_kernel(const float* __restrict__ qw,
                                                     const float* __restrict__ kw,
                                                     const float* __restrict__ vw,
                                                     const float* __restrict__ ow) {
    int i4 = (blockIdx.x * 256 + threadIdx.x) * 4;
    #pragma unroll
    for (int w = 0; w < 4; w++) {
        const float* src = (w == 0) ? qw : (w == 1) ? kw : (w == 2) ? vw : ow;
        float4 v = *(const float4*)(src + i4);
        uint2 p;
        p.x = pack2(v.y, v.x);
        p.y = pack2(v.w, v.z);
        *(uint2*)(g_wr + w * WELEMS + i4) = p;
    }
}

// ---------------------------------------------------------------------------
// GroupNorm (per batch-chunk; single-pass, x tile cached in smem)
// ---------------------------------------------------------------------------
#define XS_STR 1032
#define PREP_SMEM (16 * XS_STR * 4)   // 66048 B

__global__ __launch_bounds__(256) void gn_kernel(const float* __restrict__ x,
                                                 const float* __restrict__ gw,
                                                 const float* __restrict__ gb,
                                                 int b0) {
    extern __shared__ float xs[];
    int bg = blockIdx.x;
    int b = b0 + (bg >> 5), g = bg & 31;
    const float* xp = x + ((size_t)b * CCH + g * 16) * NTOK;
    const float4* xp4 = (const float4*)xp;

    float s = 0.f, ss = 0.f;
    #pragma unroll
    for (int it = 0; it < 16; it++) {
        int idx4 = threadIdx.x + it * 256;
        int c = idx4 >> 8, q = idx4 & 255;
        float4 v = xp4[c * 256 + q];
        *(float4*)&xs[c * XS_STR + q * 4] = v;
        s += v.x + v.y + v.z + v.w;
        ss += v.x * v.x + v.y * v.y + v.z * v.z + v.w * v.w;
    }
    __shared__ float rs[8], rss[8];
    #pragma unroll
    for (int o = 16; o > 0; o >>= 1) {
        s  += __shfl_xor_sync(~0u, s,  o);
        ss += __shfl_xor_sync(~0u, ss, o);
    }
    int wid = threadIdx.x >> 5, lane = threadIdx.x & 31;
    if (lane == 0) { rs[wid] = s; rss[wid] = ss; }
    __syncthreads();
    if (wid == 0) {
        s  = (lane < 8) ? rs[lane]  : 0.f;
        ss = (lane < 8) ? rss[lane] : 0.f;
        #pragma unroll
        for (int o = 4; o > 0; o >>= 1) {
            s  += __shfl_xor_sync(~0u, s,  o);
            ss += __shfl_xor_sync(~0u, ss, o);
        }
        if (lane == 0) { rs[0] = s; rss[0] = ss; }
    }
    __syncthreads();
    const float inv_n = 1.f / (16.f * NTOK);
    float mu  = rs[0] * inv_n;
    float var = rss[0] * inv_n - mu * mu;
    float inv = rsqrtf(var + EPS);

    __shared__ float ts[16][65];
    __shared__ float wc[16], bc[16];
    if (threadIdx.x < 16) {
        wc[threadIdx.x] = gw[g * 16 + threadIdx.x] * inv;
        bc[threadIdx.x] = gb[g * 16 + threadIdx.x];
    }
    __syncthreads();

    for (int j = 0; j < 16; j++) {
        for (int idx = threadIdx.x; idx < 1024; idx += 256) {
            int c = idx >> 6, n = idx & 63;
            float v = xs[c * XS_STR + j * 64 + n];
            ts[c][n] = (v - mu) * wc[c] + bc[c];
        }
        __syncthreads();
        for (int idx = threadIdx.x; idx < 1024; idx += 256) {
            int n = idx >> 4, c = idx & 15;
            g_xnt[((size_t)b * NTOK + j * 64 + n) * CCH + g * 16 + c] =
                __float2bfloat16(ts[c][n]);
        }
        __syncthreads();
    }
}

// ---------------------------------------------------------------------------
// Merged QKV projection (batch-chunk). blockIdx.y: 0-3 Q, 4-7 K, 8-11 V.
// ---------------------------------------------------------------------------
__global__ __launch_bounds__(256, 2) void qkv_kernel(const bf16* __restrict__ X,
                                                     const float* __restrict__ qb,
                                                     const float* __restrict__ kb,
                                                     const float* __restrict__ vb,
                                                     int b0) {
    extern __shared__ bf16 smb[];
    int n0 = blockIdx.x * 128, y = blockIdx.y, b = b0 + blockIdx.z;
    int m0 = y * 128;
    float acc[4][4][4];
    gemm_bf16(smb, g_wr + (size_t)m0 * CCH, CCH,
              X + ((size_t)b * NTOK + n0) * CCH, CCH, acc);

    int tid = threadIdx.x, wid = tid >> 5, lane = tid & 31;
    int g = lane >> 2, t = lane & 3;
    int wm0 = (wid >> 2) * 64, wn0 = (wid & 3) * 32;

    if (y < 8) {
        float scale = (y < 4) ? QSCALE : 1.0f;
        const float* bias = (y < 4) ? qb : kb;
        bf16* out = (y < 4) ? g_qt : g_kt;
        int mb = m0 & 511;
        #pragma unroll
        for (int mi = 0; mi < 4; mi++) {
            int m = wm0 + mi * 16 + g;
            float b0v = bias[mb + m], b1v = bias[mb + m + 8];
            #pragma unroll
            for (int ni = 0; ni < 4; ni++) {
                const float* c = acc[mi][ni];
                int n = wn0 + ni * 8 + t * 2;
                smb[n * 136 + m]           = __float2bfloat16((c[0] + b0v) * scale);
                smb[(n + 1) * 136 + m]     = __float2bfloat16((c[1] + b0v) * scale);
                smb[n * 136 + m + 8]       = __float2bfloat16((c[2] + b1v) * scale);
                smb[(n + 1) * 136 + m + 8] = __float2bfloat16((c[3] + b1v) * scale);
            }
        }
        __syncthreads();
        bf16* ob = out + ((size_t)b * NTOK + n0) * CCH + mb;
        #pragma unroll
        for (int it = 0; it < 8; it++) {
            int idx = tid + it * 256;
            int n = idx >> 4, c8 = (idx & 15) * 8;
            float4 v = *(const float4*)(smb + n * 136 + c8);
            *(float4*)(ob + (size_t)n * CCH + c8) = v;
        }
    } else {
        int mb = m0 - 1024;
        #pragma unroll
        for (int mi = 0; mi < 4; mi++) {
            int m = wm0 + mi * 16 + g;
            float b0v = vb[mb + m], b1v = vb[mb + m + 8];
            #pragma unroll
            for (int ni = 0; ni < 4; ni++) {
                const float* c = acc[mi][ni];
                int n = wn0 + ni * 8 + t * 2;
                *(uint32_t*)&smb[m * 136 + n]       = pack2(c[1] + b0v, c[0] + b0v);
                *(uint32_t*)&smb[(m + 8) * 136 + n] = pack2(c[3] + b1v, c[2] + b1v);
            }
        }
        __syncthreads();
        bf16* ob = g_v + ((size_t)b * CCH + mb) * NTOK + n0;
        #pragma unroll
        for (int it = 0; it < 8; it++) {
            int idx = tid + it * 256;
            int m = idx >> 4, n8 = (idx & 15) * 8;
            float4 v = *(const float4*)(smb + m * 136 + n8);
            *(float4*)(ob + (size_t)m * NTOK + n8) = v;
        }
    }
}

// ---------------------------------------------------------------------------
// Output projection (batch-chunk): fp32 out + bias + residual
// ---------------------------------------------------------------------------
__global__ __launch_bounds__(256, 2) void conv_o_kernel(const bf16* __restrict__ X,
                                                        const float* __restrict__ bias,
                                                        const float* __restrict__ resid,
                                                        float* __restrict__ out,
                                                        int b0) {
    extern __shared__ bf16 smb[];
    int n0 = blockIdx.x * 128, m0 = blockIdx.y * 128, b = b0 + blockIdx.z;
    float acc[4][4][4];
    gemm_bf16(smb, g_wr + 3 * WELEMS + (size_t)m0 * CCH, CCH,
              X + ((size_t)b * NTOK + n0) * CCH, CCH, acc);

    int tid = threadIdx.x, wid = tid >> 5, lane = tid & 31;
    int g = lane >> 2, t = lane & 3;
    int wm0 = (wid >> 2) * 64, wn0 = (wid & 3) * 32;

    float* smf = (float*)smb;
    #pragma unroll
    for (int mi = 0; mi < 4; mi++) {
        int m = wm0 + mi * 16 + g;
        float b0v = bias[m0 + m], b1v = bias[m0 + m + 8];
        #pragma unroll
        for (int ni = 0; ni < 4; ni++) {
            const float* c = acc[mi][ni];
            int n = wn0 + ni * 8 + t * 2;
            smf[m * 132 + n]           = c[0] + b0v;
            smf[m * 132 + n + 1]       = c[1] + b0v;
            smf[(m + 8) * 132 + n]     = c[2] + b1v;
            smf[(m + 8) * 132 + n + 1] = c[3] + b1v;
        }
    }
    __syncthreads();

    #pragma unroll
    for (int it = 0; it < 16; it++) {
        int idx4 = tid + it * 256;
        int m = idx4 >> 5, nq = (idx4 & 31) * 4;
        size_t o = ((size_t)b * CCH + m0 + m) * NTOK + n0 + nq;
        float4 r = *(const float4*)&resid[o];
        float4 v = make_float4(smf[m * 132 + nq]     + r.x,
                               smf[m * 132 + nq + 1] + r.y,
                               smf[m * 132 + nq + 2] + r.z,
                               smf[m * 132 + nq + 3] + r.w);
        *(float4*)&out[o] = v;
    }
}

// ---------------------------------------------------------------------------
// Fused flash attention (batch-chunk), no-max softmax in bf16 (ex2.bf16x2),
// row-sum via ones-MMA. CTA = (128 queries, bh), kv tiles 64, 3-stage.
// ---------------------------------------------------------------------------
#define KSTR 72
#define FSTG (2 * 64 * KSTR)
#define VOFF (64 * KSTR * 2)
#define FLASH_SMEM ((128 * KSTR + 3 * FSTG) * 2)  // 73728 B
#define ONES2 0x3F803F80u

__device__ __forceinline__ void load_kv(bf16* dst, const bf16* ksrc,
                                        const bf16* vsrc, int tid) {
    #pragma unroll
    for (int it = 0; it < 2; it++) {
        int idx = tid + it * 256;
        int r = idx >> 3, c = (idx & 7) * 8;
        cp16(smem_u32(dst + r * KSTR + c), ksrc + (size_t)r * CCH + c);
    }
    bf16* vd = dst + 64 * KSTR;
    #pragma unroll
    for (int it = 0; it < 2; it++) {
        int idx = tid + it * 256;
        int r = idx >> 3, c = (idx & 7) * 8;
        cp16(smem_u32(vd + r * KSTR + c), vsrc + (size_t)r * NTOK + c);
    }
}

__global__ __launch_bounds__(256, 2) void flash_kernel(int bh0) {
    extern __shared__ bf16 smb[];
    bf16* Qs = smb;
    bf16* St = smb + 128 * KSTR;

    int q0 = blockIdx.x * 128, bh = bh0 + blockIdx.y;
    int b = bh >> 3, h = bh & 7;
    const bf16* qp = g_qt + ((size_t)b * NTOK + q0) * CCH + h * HD;
    const bf16* kp = g_kt + (size_t)b * NTOK * CCH + h * HD;
    const bf16* vp = g_v + ((size_t)b * CCH + h * HD) * NTOK;

    int tid = threadIdx.x, wid = tid >> 5, lane = tid & 31;
    int g = lane >> 2, t = lane & 3;
    int wm = wid * 16;
    int arow = (lane & 7) + ((lane >> 3) & 1) * 8;
    int acol = (lane >> 4) * 8;
    int brow = (lane & 7) + ((lane >= 16) ? 8 : 0);
    int bcol = ((lane >> 3) & 1) * 8;

    #pragma unroll
    for (int it = 0; it < 4; it++) {
        int idx = tid + it * 256;
        int r = idx >> 3, c = (idx & 7) * 8;
        cp16(smem_u32(Qs + r * KSTR + c), qp + (size_t)r * CCH + c);
    }
    load_kv(St, kp, vp, tid);
    cp_commit();
    load_kv(St + FSTG, kp + (size_t)64 * CCH, vp + 64, tid);
    cp_commit();

    uint32_t kbase[4];
    #pragma unroll
    for (int np = 0; np < 4; np++)
        kbase[np] = smem_u32(St + (np * 16 + brow) * KSTR + bcol);

    float oacc[8][4];
    #pragma unroll
    for (int ni = 0; ni < 8; ni++)
        #pragma unroll
        for (int r = 0; r < 4; r++) oacc[ni][r] = 0.f;
    float lacc[4] = {0.f, 0.f, 0.f, 0.f};
    const uint32_t ones[2] = {ONES2, ONES2};
    uint32_t qf[4][4];

    for (int kt = 0; kt < 16; kt++) {
        cp_wait<1>();
        __syncthreads();
        if (kt + 2 < 16)
            load_kv(St + ((kt + 2) % 3) * FSTG,
                    kp + (size_t)(kt + 2) * 64 * CCH, vp + (kt + 2) * 64, tid);
        cp_commit();

        if (kt == 0) {
            #pragma unroll
            for (int ks = 0; ks < 4; ks++)
                ldsm_x4(qf[ks], smem_u32(Qs + (wm + arow) * KSTR + ks * 16 + acol));
        }
        uint32_t stoff = (uint32_t)((kt % 3) * (FSTG * 2));

        float sacc[8][4];
        #pragma unroll
        for (int nt = 0; nt < 8; nt++)
            #pragma unroll
            for (int r = 0; r < 4; r++) sacc[nt][r] = 0.f;
        #pragma unroll
        for (int ks = 0; ks < 4; ks++) {
            #pragma unroll
            for (int np = 0; np < 4; np++) {
                uint32_t bq[4];
                ldsm_x4(bq, kbase[np] + stoff + ks * 32);
                mma_bf16(sacc[2 * np],     qf[ks], bq);
                mma_bf16(sacc[2 * np + 1], qf[ks], bq + 2);
            }
        }

        #pragma unroll
        for (int j = 0; j < 4; j++) {
            uint32_t pf[4];
            pf[0] = ex2_bf16x2(pack2(sacc[2 * j][1],     sacc[2 * j][0]));
            pf[1] = ex2_bf16x2(pack2(sacc[2 * j][3],     sacc[2 * j][2]));
            pf[2] = ex2_bf16x2(pack2(sacc[2 * j + 1][1], sacc[2 * j + 1][0]));
            pf[3] = ex2_bf16x2(pack2(sacc[2 * j + 1][3], sacc[2 * j + 1][2]));
            mma_bf16(lacc, pf, ones);
            #pragma unroll
            for (int np = 0; np < 4; np++) {
                uint32_t bq[4];
                ldsm_x4(bq, kbase[np] + stoff + VOFF + j * 32);
                mma_bf16(oacc[2 * np],     pf, bq);
                mma_bf16(oacc[2 * np + 1], pf, bq + 2);
            }
        }
    }

    float i0 = 1.f / lacc[0], i1 = 1.f / lacc[2];
    bf16* ob = g_aot + ((size_t)b * NTOK + q0 + wm) * CCH + h * HD;
    #pragma unroll
    for (int ni = 0; ni < 8; ni++) {
        int d = ni * 8 + t * 2;
        *(__nv_bfloat162*)(ob + (size_t)g * CCH + d) =
            __floats2bfloat162_rn(oacc[ni][0] * i0, oacc[ni][1] * i0);
        *(__nv_bfloat162*)(ob + (size_t)(g + 8) * CCH + d) =
            __floats2bfloat162_rn(oacc[ni][2] * i1, oacc[ni][3] * i1);
    }
}

// ---------------------------------------------------------------------------
extern "C" void kernel_launch(void* const* d_in, const int* in_sizes, int n_in,
                              void* d_out, int out_size) {
    const float* x   = (const float*)d_in[0];
    const float* gnw = (const float*)d_in[1];
    const float* gnb = (const float*)d_in[2];
    const float* qw  = (const float*)d_in[3];
    const float* qb  = (const float*)d_in[4];
    const float* kw  = (const float*)d_in[5];
    const float* kb  = (const float*)d_in[6];
    const float* vw  = (const float*)d_in[7];
    const float* vb  = (const float*)d_in[8];
    const float* ow  = (const float*)d_in[9];
    const float* ob  = (const float*)d_in[10];
    float* out = (float*)d_out;

    void *p_xnt, *p_aot;
    cudaGetSymbolAddress(&p_xnt, g_xnt);
    cudaGetSymbolAddress(&p_aot, g_aot);
    bf16* xnt = (bf16*)p_xnt;
    bf16* aot = (bf16*)p_aot;

    // One-time host resources: 3-chain topology (2 created streams, 4 events)
    static cudaStream_t s1 = nullptr, s2 = nullptr;
    static cudaEvent_t evFork = nullptr, evW = nullptr;
    static cudaEvent_t evJ1 = nullptr, evJ2 = nullptr;
    if (!s1) {
        cudaStreamCreateWithFlags(&s1, cudaStreamNonBlocking);
        cudaStreamCreateWithFlags(&s2, cudaStreamNonBlocking);
        cudaEventCreateWithFlags(&evFork, cudaEventDisableTiming);
        cudaEventCreateWithFlags(&evW,    cudaEventDisableTiming);
        cudaEventCreateWithFlags(&evJ1,   cudaEventDisableTiming);
        cudaEventCreateWithFlags(&evJ2,   cudaEventDisableTiming);
        cudaFuncSetAttribute(gn_kernel,     cudaFuncAttributeMaxDynamicSharedMemorySize, PREP_SMEM);
        cudaFuncSetAttribute(qkv_kernel,    cudaFuncAttributeMaxDynamicSharedMemorySize, GEMM_SMEM);
        cudaFuncSetAttribute(conv_o_kernel, cudaFuncAttributeMaxDynamicSharedMemorySize, GEMM_SMEM);
        cudaFuncSetAttribute(flash_kernel,  cudaFuncAttributeMaxDynamicSharedMemorySize, FLASH_SMEM);
    }

    // Fork
    cudaEventRecord(evFork, 0);
    cudaStreamWaitEvent(s1, evFork, 0);
    cudaStreamWaitEvent(s2, evFork, 0);

    // Chains: c0 = batches 0-2 (default stream), c1 = batches 3-5 (s1),
    //         c2 = batches 6-7 (s2, lightest, owns prep_w)
    dim3 gq3(NTOK / 128, 12, 3), gq2(NTOK / 128, 12, 2);
    dim3 gf3(NTOK / 128, 3 * HEADS), gf2(NTOK / 128, 2 * HEADS);
    dim3 gg3(NTOK / 128, CCH / 128, 3), gg2(NTOK / 128, CCH / 128, 2);

    // Chain 2 (s2): weights first, then its 2-batch chain
    prep_w_kernel<<<256, 256, 0, s2>>>(qw, kw, vw, ow);
    cudaEventRecord(evW, s2);
    gn_kernel<<<64, 256, PREP_SMEM, s2>>>(x, gnw, gnb, 6);
    qkv_kernel<<<gq2, 256, GEMM_SMEM, s2>>>(xnt, qb, kb, vb, 6);
    flash_kernel<<<gf2, 256, FLASH_SMEM, s2>>>(48);
    conv_o_kernel<<<gg2, 256, GEMM_SMEM, s2>>>(aot, ob, x, out, 6);

    // Chain 0 (default): GN immediately, wait weights, 3-batch chain
    gn_kernel<<<96, 256, PREP_SMEM>>>(x, gnw, gnb, 0);
    cudaStreamWaitEvent(0, evW, 0);
    qkv_kernel<<<gq3, 256, GEMM_SMEM>>>(xnt, qb, kb, vb, 0);
    flash_kernel<<<gf3, 256, FLASH_SMEM>>>(0);
    conv_o_kernel<<<gg3, 256, GEMM_SMEM>>>(aot, ob, x, out, 0);

    // Chain 1 (s1): GN immediately, wait weights, 3-batch chain
    gn_kernel<<<96, 256, PREP_SMEM, s1>>>(x, gnw, gnb, 3);
    cudaStreamWaitEvent(s1, evW, 0);
    qkv_kernel<<<gq3, 256, GEMM_SMEM, s1>>>(xnt, qb, kb, vb, 3);
    flash_kernel<<<gf3, 256, FLASH_SMEM, s1>>>(24);
    conv_o_kernel<<<gg3, 256, GEMM_SMEM, s1>>>(aot, ob, x, out, 3);

    // Join
    cudaEventRecord(evJ1, s1);
    cudaStreamWaitEvent(0, evJ1, 0);
    cudaEventRecord(evJ2, s2);
    cudaStreamWaitEvent(0, evJ2, 0);
}